// round 8
// baseline (speedup 1.0000x reference)
#include <cuda_runtime.h>
#include <cstdint>
#include <cstddef>

#define BMAX 32768

// ---------------- device scratch (uninitialized globals; no allocations) ----------------
__device__ float g_x[BMAX * 64];              // tanh features of cond MLP
__device__ float g_cond[3 * BMAX * 256];      // [0]=b_mod, [1]=c_mod, [2]=w_scale
__device__ float g_v[BMAX * 256];             // model visible state (0/1 floats)
__device__ float g_h[BMAX * 256];             // h * w_scale
__device__ float g_t[BMAX * 256];             // v @ W scratch for free energy
__device__ float g_WT[256 * 256];             // W transposed
__device__ float g_P[64 * 768];               // combined cond-param weights, [k][n]
__device__ float g_pb[768];                   // combined cond-param bias
__device__ float g_Wsum[256];                 // W.sum(axis=0)
__device__ float g_part[BMAX / 4];            // block partial sums (2 * B/8)

// ---------------- packed f32x2 FMA (Blackwell) ----------------
#define FFMA2_(d, a, b) \
    asm("fma.rn.f32x2 %0, %1, %2, %0;" : "+l"(d) : "l"(a), "l"(b))
#define PACK2_DUP_(d, s) \
    asm("mov.b64 %0, {%1, %1};" : "=l"(d) : "f"(s))
#define UNPACK2_(lo, hi, s) \
    asm("mov.b64 {%0, %1}, %2;" : "=f"(lo), "=f"(hi) : "l"(s))

// ---------------- threefry2x32-20 (exact JAX PRNG) ----------------
__host__ __device__ inline uint32_t rotl32(uint32_t v, int d) {
    return (v << d) | (v >> (32 - d));
}

__host__ __device__ inline void tf2x32(uint32_t k0, uint32_t k1, uint32_t& x0, uint32_t& x1) {
    uint32_t ks2 = k0 ^ k1 ^ 0x1BD11BDAu;
    x0 += k0; x1 += k1;
    x0 += x1; x1 = rotl32(x1, 13); x1 ^= x0;
    x0 += x1; x1 = rotl32(x1, 15); x1 ^= x0;
    x0 += x1; x1 = rotl32(x1, 26); x1 ^= x0;
    x0 += x1; x1 = rotl32(x1,  6); x1 ^= x0;
    x0 += k1;  x1 += ks2 + 1u;
    x0 += x1; x1 = rotl32(x1, 17); x1 ^= x0;
    x0 += x1; x1 = rotl32(x1, 29); x1 ^= x0;
    x0 += x1; x1 = rotl32(x1, 16); x1 ^= x0;
    x0 += x1; x1 = rotl32(x1, 24); x1 ^= x0;
    x0 += ks2; x1 += k0 + 2u;
    x0 += x1; x1 = rotl32(x1, 13); x1 ^= x0;
    x0 += x1; x1 = rotl32(x1, 15); x1 ^= x0;
    x0 += x1; x1 = rotl32(x1, 26); x1 ^= x0;
    x0 += x1; x1 = rotl32(x1,  6); x1 ^= x0;
    x0 += k0;  x1 += k1 + 3u;
    x0 += x1; x1 = rotl32(x1, 17); x1 ^= x0;
    x0 += x1; x1 = rotl32(x1, 29); x1 ^= x0;
    x0 += x1; x1 = rotl32(x1, 16); x1 ^= x0;
    x0 += x1; x1 = rotl32(x1, 24); x1 ^= x0;
    x0 += k1;  x1 += ks2 + 4u;
    x0 += x1; x1 = rotl32(x1, 13); x1 ^= x0;
    x0 += x1; x1 = rotl32(x1, 15); x1 ^= x0;
    x0 += x1; x1 = rotl32(x1, 26); x1 ^= x0;
    x0 += x1; x1 = rotl32(x1,  6); x1 ^= x0;
    x0 += ks2; x1 += k0 + 5u;
}

// Single-element uniform (used where pairing is awkward)
__device__ inline float tf_uniform(uint32_t k0, uint32_t k1, uint32_t f, uint32_t half) {
    uint32_t sec = (f >= half) ? 1u : 0u;
    uint32_t lane = sec ? (f - half) : f;
    uint32_t x0 = lane, x1 = lane + half;
    tf2x32(k0, k1, x0, x1);
    uint32_t bits = sec ? x1 : x0;
    return __uint_as_float((bits >> 9) | 0x3f800000u) - 1.0f;
}

// Paired uniform: one cipher yields u(f) and u(f+half) for f < half.
__device__ inline void tf_uniform2(uint32_t k0, uint32_t k1, uint32_t f, uint32_t half,
                                   float& u0, float& u1) {
    uint32_t x0 = f, x1 = f + half;
    tf2x32(k0, k1, x0, x1);
    u0 = __uint_as_float((x0 >> 9) | 0x3f800000u) - 1.0f;
    u1 = __uint_as_float((x1 >> 9) | 0x3f800000u) - 1.0f;
}

__device__ inline float sigmoidf_(float x) {
    float e = expf(-fabsf(x));
    float s = 1.0f / (1.0f + e);
    return (x >= 0.0f) ? s : (1.0f - s);
}

__device__ inline float softplusf_(float x) {
    return fmaxf(x, 0.0f) + log1pf(expf(-fabsf(x)));
}

// ---------------- prep: WT, Wsum, combined cond-param weights ----------------
__global__ void __launch_bounds__(256) prep_kernel(
    const float* __restrict__ W, const float* __restrict__ b, const float* __restrict__ c,
    const float* __restrict__ fc2w, const float* __restrict__ fc2b,
    float* __restrict__ WT, float* __restrict__ P, float* __restrict__ pb,
    float* __restrict__ Wsum)
{
    int idx = blockIdx.x * blockDim.x + threadIdx.x;
    int stride = gridDim.x * blockDim.x;
    for (int i = idx; i < 256 * 256; i += stride) {
        int k = i >> 8, cc = i & 255;
        WT[k * 256 + cc] = W[cc * 256 + k];
    }
    for (int i = idx; i < 64 * 768; i += stride) {
        int k = i / 768, n = i % 768;
        float val;
        if (n < 256)      val = b[n] * fc2w[n * 64 + k] + fc2w[(256 + n) * 64 + k];
        else if (n < 512) { int j = n - 256; val = c[j] * fc2w[(512 + j) * 64 + k] + fc2w[(768 + j) * 64 + k]; }
        else              { int j = n - 512; val = fc2w[(1024 + j) * 64 + k]; }
        P[k * 768 + n] = val;
    }
    for (int i = idx; i < 768; i += stride) {
        float val;
        if (i < 256)      val = b[i] * (1.0f + fc2b[i]) + fc2b[256 + i];
        else if (i < 512) { int j = i - 256; val = c[j] * (1.0f + fc2b[512 + j]) + fc2b[768 + j]; }
        else              { int j = i - 512; val = fc2b[1024 + j]; }
        pb[i] = val;
    }
    for (int i = idx; i < 256; i += stride) {
        float s = 0.0f;
        for (int rr = 0; rr < 256; rr++) s += W[rr * 256 + i];
        Wsum[i] = s;
    }
}

// ---------------- x = tanh(cond @ fc1_w.T + fc1_b), [B,64]x[64,64] ----------------
__global__ void __launch_bounds__(256) cond_fc1_kernel(
    const float* __restrict__ cond, const float* __restrict__ fc1w,
    const float* __restrict__ fc1b, float* __restrict__ xout)
{
    __shared__ float Cs[64][65];
    __shared__ float Ws[64][65];
    int t = threadIdx.x;
    int r0 = blockIdx.x * 64;
#pragma unroll
    for (int l = 0; l < 4; l++) {
        int id = t + l * 256;
        int j = id >> 4, k4 = (id & 15) << 2;
        float4 w = *(const float4*)(fc1w + j * 64 + k4);
        Ws[k4 + 0][j] = w.x; Ws[k4 + 1][j] = w.y; Ws[k4 + 2][j] = w.z; Ws[k4 + 3][j] = w.w;
    }
#pragma unroll
    for (int l = 0; l < 4; l++) {
        int id = t + l * 256;
        int i = id >> 4, k4 = (id & 15) << 2;
        float4 v = *(const float4*)(cond + (size_t)(r0 + i) * 64 + k4);
        Cs[i][k4 + 0] = v.x; Cs[i][k4 + 1] = v.y; Cs[i][k4 + 2] = v.z; Cs[i][k4 + 3] = v.w;
    }
    __syncthreads();
    int tx = t & 15, ty = t >> 4;
    float acc[4][4];
#pragma unroll
    for (int i = 0; i < 4; i++)
#pragma unroll
        for (int j = 0; j < 4; j++) acc[i][j] = 0.0f;
#pragma unroll 8
    for (int k = 0; k < 64; k++) {
        float a[4], bv[4];
#pragma unroll
        for (int i = 0; i < 4; i++) a[i] = Cs[ty * 4 + i][k];
#pragma unroll
        for (int j = 0; j < 4; j++) bv[j] = Ws[k][tx * 4 + j];
#pragma unroll
        for (int i = 0; i < 4; i++)
#pragma unroll
            for (int j = 0; j < 4; j++) acc[i][j] = fmaf(a[i], bv[j], acc[i][j]);
    }
#pragma unroll
    for (int i = 0; i < 4; i++) {
        int r = r0 + ty * 4 + i;
#pragma unroll
        for (int j = 0; j < 4; j++) {
            int jj = tx * 4 + j;
            xout[(size_t)r * 64 + jj] = tanhf(acc[i][j] + fc1b[jj]);
        }
    }
}

// ---------------- v_model init: noise rows (threefry) + copy of v_data ----------------
__global__ void __launch_bounds__(256) init_v_kernel(
    const float* __restrict__ vdata, float* __restrict__ v,
    int B, int n_noise, uint32_t k0, uint32_t k1)
{
    int total = B * 256;
    uint32_t half = (uint32_t)(n_noise * 128);
    for (int idx = blockIdx.x * blockDim.x + threadIdx.x; idx < total;
         idx += gridDim.x * blockDim.x) {
        int r = idx >> 8;
        float val;
        if (r < n_noise) {
            float u = tf_uniform(k0, k1, (uint32_t)idx, half);
            val = (u < 0.5f) ? 1.0f : 0.0f;
        } else {
            val = vdata[idx];
        }
        v[idx] = val;
    }
}

// ---------------- 128x128x16 SGEMM, f32x2, split-row tiles, paired RNG ----------------
// Tile rows 0..63 map to global rows by*64+r (low half of M), rows 64..127 map to
// M/2 + by*64 + r (high half). Each thread owns matching low/high rows so one
// threefry cipher serves both elements of a JAX-uniform pair.
// Double-buffered smem, one __syncthreads per K-tile. Bs pre-duplicated to f32x2.
// MODE 0: cond params (N=768); MODE 1: h-sample (stores h*w_scale);
// MODE 2: v-sample; MODE 3: plain store.
#define SGEMM_SMEM (2 * 16 * 132 * 4 + 2 * 16 * 128 * 8)

template <int MODE>
__global__ void __launch_bounds__(256, 2) sgemm_kernel(
    const float* __restrict__ A, const float* __restrict__ Bm,
    float* __restrict__ out,
    const float* __restrict__ e0, const float* __restrict__ e1,
    int M, int N, int K,
    uint32_t rk0, uint32_t rk1, uint32_t half)
{
    extern __shared__ char smem_raw[];
    typedef float AsT[16][132];
    typedef unsigned long long BsT[16][128];
    AsT* As = (AsT*)smem_raw;                               // As[0..1][k][row]
    BsT* Bs2 = (BsT*)(smem_raw + 2 * 16 * 132 * 4);         // Bs2[0..1][k][n], dup f32x2

    const int t = threadIdx.x;
    const int tx = t & 15, ty = t >> 4;
    const int bx = blockIdx.x, by = blockIdx.y;
    const int Mh = M >> 1;
    const float* Bb = Bm + (size_t)bx * 128;

    // A-load lanes: thread loads row lrow (low half) and 64+lrow (high half)
    const int lrow = t >> 2;
    const int lc4 = (t & 3) << 2;
    const float* Arow0 = A + (size_t)(by * 64 + lrow) * K + lc4;
    const float* Arow1 = A + (size_t)(Mh + by * 64 + lrow) * K + lc4;
    // B-load lanes
    const int bkk = t >> 5;
    const int bn4 = (t & 31) << 2;

    unsigned long long acc2[4][8];
#pragma unroll
    for (int i = 0; i < 4; i++)
#pragma unroll
        for (int j = 0; j < 8; j++) acc2[i][j] = 0ull;

    float4 ra0 = *(const float4*)(Arow0);
    float4 ra1 = *(const float4*)(Arow1);
    float4 rb0 = *(const float4*)(Bb + (size_t)bkk * N + bn4);
    float4 rb1 = *(const float4*)(Bb + (size_t)(bkk + 8) * N + bn4);

    auto stage = [&](int buf) {
        As[buf][lc4 + 0][lrow] = ra0.x; As[buf][lc4 + 1][lrow] = ra0.y;
        As[buf][lc4 + 2][lrow] = ra0.z; As[buf][lc4 + 3][lrow] = ra0.w;
        As[buf][lc4 + 0][64 + lrow] = ra1.x; As[buf][lc4 + 1][64 + lrow] = ra1.y;
        As[buf][lc4 + 2][64 + lrow] = ra1.z; As[buf][lc4 + 3][64 + lrow] = ra1.w;
        unsigned long long d;
        PACK2_DUP_(d, rb0.x); Bs2[buf][bkk][bn4 + 0] = d;
        PACK2_DUP_(d, rb0.y); Bs2[buf][bkk][bn4 + 1] = d;
        PACK2_DUP_(d, rb0.z); Bs2[buf][bkk][bn4 + 2] = d;
        PACK2_DUP_(d, rb0.w); Bs2[buf][bkk][bn4 + 3] = d;
        PACK2_DUP_(d, rb1.x); Bs2[buf][bkk + 8][bn4 + 0] = d;
        PACK2_DUP_(d, rb1.y); Bs2[buf][bkk + 8][bn4 + 1] = d;
        PACK2_DUP_(d, rb1.z); Bs2[buf][bkk + 8][bn4 + 2] = d;
        PACK2_DUP_(d, rb1.w); Bs2[buf][bkk + 8][bn4 + 3] = d;
    };

    const int T = K >> 4;
    stage(0);
    __syncthreads();

    for (int tile = 0; tile < T; tile++) {
        const int buf = tile & 1;
        if (tile + 1 < T) {
            const int ko = (tile + 1) * 16;
            ra0 = *(const float4*)(Arow0 + ko);
            ra1 = *(const float4*)(Arow1 + ko);
            rb0 = *(const float4*)(Bb + (size_t)(ko + bkk) * N + bn4);
            rb1 = *(const float4*)(Bb + (size_t)(ko + bkk + 8) * N + bn4);
        }
#pragma unroll
        for (int kk = 0; kk < 16; kk++) {
            unsigned long long a2[4];
            a2[0] = *(const unsigned long long*)&As[buf][kk][ty * 4];
            a2[1] = *(const unsigned long long*)&As[buf][kk][ty * 4 + 2];
            a2[2] = *(const unsigned long long*)&As[buf][kk][64 + ty * 4];
            a2[3] = *(const unsigned long long*)&As[buf][kk][64 + ty * 4 + 2];
#pragma unroll
            for (int j = 0; j < 8; j++) {
                unsigned long long b2 = Bs2[buf][kk][tx + 16 * j];
                FFMA2_(acc2[0][j], a2[0], b2);
                FFMA2_(acc2[1][j], a2[1], b2);
                FFMA2_(acc2[2][j], a2[2], b2);
                FFMA2_(acc2[3][j], a2[3], b2);
            }
        }
        if (tile + 1 < T) {
            stage(buf ^ 1);
            __syncthreads();
        }
    }

    // epilogue: thread owns low rows (by*64+ty*4+q) and high rows (Mh + same), q=0..3
#pragma unroll
    for (int p = 0; p < 2; p++) {
#pragma unroll
        for (int j = 0; j < 8; j++) {
            const int c = bx * 128 + tx + 16 * j;
            float vl0, vl1, vh0, vh1;
            UNPACK2_(vl0, vl1, acc2[p][j]);      // low rows, q = 2p, 2p+1
            UNPACK2_(vh0, vh1, acc2[2 + p][j]);  // high rows, same q
#pragma unroll
            for (int q2 = 0; q2 < 2; q2++) {
                const int q = 2 * p + q2;
                const int rL = by * 64 + ty * 4 + q;
                const int rH = Mh + rL;
                const float vlow = q2 ? vl1 : vl0;
                const float vhigh = q2 ? vh1 : vh0;
                if (MODE == 0) {
                    float bias = e0[c];
                    float valL = vlow + bias;
                    float valH = vhigh + bias;
                    if (c >= 512) {
                        valL = 1.0f + 0.05f * tanhf(valL);
                        valH = 1.0f + 0.05f * tanhf(valH);
                    }
                    size_t o0 = (size_t)(c >> 8) * M * 256 + (c & 255);
                    out[o0 + (size_t)rL * 256] = valL;
                    out[o0 + (size_t)rH * 256] = valH;
                } else if (MODE == 3) {
                    out[(size_t)rL * 256 + c] = vlow;
                    out[(size_t)rH * 256 + c] = vhigh;
                } else {
                    size_t iL = (size_t)rL * 256 + c;
                    size_t iH = (size_t)rH * 256 + c;   // == iL + half
                    float u0, u1;
                    tf_uniform2(rk0, rk1, (uint32_t)iL, half, u0, u1);
                    if (MODE == 1) {
                        float wsL = e0[iL], wsH = e0[iH];
                        float pL = sigmoidf_(fmaf(vlow, wsL, e1[iL]));
                        float pH = sigmoidf_(fmaf(vhigh, wsH, e1[iH]));
                        out[iL] = (u0 < pL) ? wsL : 0.0f;
                        out[iH] = (u1 < pH) ? wsH : 0.0f;
                    } else {
                        float pL = sigmoidf_(vlow + e0[iL]);
                        float pH = sigmoidf_(vhigh + e0[iH]);
                        out[iL] = (u0 < pL) ? 1.0f : 0.0f;
                        out[iH] = (u1 < pH) ? 1.0f : 0.0f;
                    }
                }
            }
        }
    }
}

// ---------------- free-energy row reduce (deterministic) ----------------
__global__ void __launch_bounds__(256) fe_reduce_kernel(
    const float* __restrict__ vw, const float* __restrict__ v,
    const float* __restrict__ bmod, const float* __restrict__ cmod,
    const float* __restrict__ ws, const float* __restrict__ Wsum,
    float sign, float* __restrict__ part, int partBase)
{
    __shared__ float sW[256];
    __shared__ float wres[8];
    int t = threadIdx.x;
    sW[t] = Wsum[t];
    __syncthreads();
    int warp = t >> 5, lane = t & 31;
    int r = blockIdx.x * 8 + warp;
    size_t base = (size_t)r * 256;
    float s2v = 0.0f, s2f = 0.0f, s1v = 0.0f, s1f = 0.0f;
#pragma unroll
    for (int jj = 0; jj < 8; jj++) {
        int c = jj * 32 + lane;
        float tt = vw[base + c];
        float w  = ws[base + c];
        float cm = cmod[base + c];
        float tv = tt * w;
        float lv = tv + cm;
        float lf = fmaf(sW[c], w, cm) - tv;
        s2v += softplusf_(lv);
        s2f += softplusf_(lf);
        float bm = bmod[base + c];
        float vv = v[base + c];
        s1v = fmaf(vv, bm, s1v);
        s1f = fmaf(1.0f - vv, bm, s1f);
    }
#pragma unroll
    for (int o = 16; o > 0; o >>= 1) {
        s2v += __shfl_xor_sync(0xffffffffu, s2v, o);
        s2f += __shfl_xor_sync(0xffffffffu, s2f, o);
        s1v += __shfl_xor_sync(0xffffffffu, s1v, o);
        s1f += __shfl_xor_sync(0xffffffffu, s1f, o);
    }
    if (lane == 0) {
        float av = s1v + s2v;
        float af = s1f + s2f;
        float mx = fmaxf(av, af);
        float fe = -(mx + log1pf(expf(-fabsf(av - af))));
        wres[warp] = sign * fe;
    }
    __syncthreads();
    if (t == 0) {
        float s = 0.0f;
#pragma unroll
        for (int w = 0; w < 8; w++) s += wres[w];
        part[partBase + blockIdx.x] = s;
    }
}

__global__ void __launch_bounds__(256) final_reduce_kernel(
    const float* __restrict__ part, int n, float invB, float* __restrict__ out)
{
    __shared__ float s[256];
    float acc = 0.0f;
    for (int i = threadIdx.x; i < n; i += 256) acc += part[i];
    s[threadIdx.x] = acc;
    __syncthreads();
    for (int o = 128; o > 0; o >>= 1) {
        if (threadIdx.x < o) s[threadIdx.x] += s[threadIdx.x + o];
        __syncthreads();
    }
    if (threadIdx.x == 0) out[0] = s[0] * invB;
}

// ---------------- host: JAX key chain ----------------
static inline void host_split2(uint32_t k0, uint32_t k1, uint32_t* ka, uint32_t* kb) {
    uint32_t a0 = 0, b0 = 2; tf2x32(k0, k1, a0, b0);
    uint32_t a1 = 1, b1 = 3; tf2x32(k0, k1, a1, b1);
    ka[0] = a0; ka[1] = a1; kb[0] = b0; kb[1] = b1;
}
static inline void host_split3(uint32_t k0, uint32_t k1,
                               uint32_t* kA, uint32_t* kB, uint32_t* kC) {
    uint32_t a0 = 0, b0 = 3; tf2x32(k0, k1, a0, b0);
    uint32_t a1 = 1, b1 = 4; tf2x32(k0, k1, a1, b1);
    uint32_t a2 = 2, b2 = 5; tf2x32(k0, k1, a2, b2);
    kA[0] = a0; kA[1] = a1;
    kB[0] = a2; kB[1] = b0;
    kC[0] = b1; kC[1] = b2;
}

extern "C" void kernel_launch(void* const* d_in, const int* in_sizes, int n_in,
                              void* d_out, int out_size)
{
    const float* v_data = (const float*)d_in[0];
    const float* cond   = (const float*)d_in[1];
    const float* W      = (const float*)d_in[2];
    const float* b      = (const float*)d_in[3];
    const float* c      = (const float*)d_in[4];
    const float* fc1w   = (const float*)d_in[5];
    const float* fc1b   = (const float*)d_in[6];
    const float* fc2w   = (const float*)d_in[7];
    const float* fc2b   = (const float*)d_in[8];

    int B = in_sizes[0] / 256;
    if (B > BMAX) B = BMAX;
    int n_noise = (int)((double)B * 0.1);

    cudaFuncSetAttribute(sgemm_kernel<0>, cudaFuncAttributeMaxDynamicSharedMemorySize, SGEMM_SMEM);
    cudaFuncSetAttribute(sgemm_kernel<1>, cudaFuncAttributeMaxDynamicSharedMemorySize, SGEMM_SMEM);
    cudaFuncSetAttribute(sgemm_kernel<2>, cudaFuncAttributeMaxDynamicSharedMemorySize, SGEMM_SMEM);
    cudaFuncSetAttribute(sgemm_kernel<3>, cudaFuncAttributeMaxDynamicSharedMemorySize, SGEMM_SMEM);

    float *p_x, *p_cond, *p_v, *p_h, *p_t, *p_WT, *p_P, *p_pb, *p_Wsum, *p_part;
    cudaGetSymbolAddress((void**)&p_x,    g_x);
    cudaGetSymbolAddress((void**)&p_cond, g_cond);
    cudaGetSymbolAddress((void**)&p_v,    g_v);
    cudaGetSymbolAddress((void**)&p_h,    g_h);
    cudaGetSymbolAddress((void**)&p_t,    g_t);
    cudaGetSymbolAddress((void**)&p_WT,   g_WT);
    cudaGetSymbolAddress((void**)&p_P,    g_P);
    cudaGetSymbolAddress((void**)&p_pb,   g_pb);
    cudaGetSymbolAddress((void**)&p_Wsum, g_Wsum);
    cudaGetSymbolAddress((void**)&p_part, g_part);
    float* p_bmod = p_cond;
    float* p_cmod = p_cond + (size_t)B * 256;
    float* p_ws   = p_cond + (size_t)2 * B * 256;

    // JAX key chain: key(42) -> split(2) -> 5x split(3)
    uint32_t rng[2] = {0u, 42u};
    uint32_t kn[2];
    host_split2(rng[0], rng[1], rng, kn);
    uint32_t k1s[5][2], k2s[5][2];
    for (int s = 0; s < 5; s++) {
        uint32_t nk[2];
        host_split3(rng[0], rng[1], nk, k1s[s], k2s[s]);
        rng[0] = nk[0]; rng[1] = nk[1];
    }

    prep_kernel<<<128, 256>>>(W, b, c, fc2w, fc2b, p_WT, p_P, p_pb, p_Wsum);
    cond_fc1_kernel<<<B / 64, 256>>>(cond, fc1w, fc1b, p_x);

    dim3 g0(6, B / 128);
    sgemm_kernel<0><<<g0, 256, SGEMM_SMEM>>>(p_x, p_P, p_cond, p_pb, nullptr,
                                             B, 768, 64, 0u, 0u, 0u);

    init_v_kernel<<<2048, 256>>>(v_data, p_v, B, n_noise, kn[0], kn[1]);

    uint32_t half = (uint32_t)B * 128u;
    dim3 g1(2, B / 128);
    for (int s = 0; s < 5; s++) {
        sgemm_kernel<1><<<g1, 256, SGEMM_SMEM>>>(p_v, W, p_h, p_ws, p_cmod,
                                                 B, 256, 256, k1s[s][0], k1s[s][1], half);
        sgemm_kernel<2><<<g1, 256, SGEMM_SMEM>>>(p_h, p_WT, p_v, p_bmod, nullptr,
                                                 B, 256, 256, k2s[s][0], k2s[s][1], half);
    }

    // free energy: data (+) and model (-)
    sgemm_kernel<3><<<g1, 256, SGEMM_SMEM>>>(v_data, W, p_t, nullptr, nullptr,
                                             B, 256, 256, 0u, 0u, 0u);
    fe_reduce_kernel<<<B / 8, 256>>>(p_t, v_data, p_bmod, p_cmod, p_ws, p_Wsum,
                                     1.0f, p_part, 0);
    sgemm_kernel<3><<<g1, 256, SGEMM_SMEM>>>(p_v, W, p_t, nullptr, nullptr,
                                             B, 256, 256, 0u, 0u, 0u);
    fe_reduce_kernel<<<B / 8, 256>>>(p_t, p_v, p_bmod, p_cmod, p_ws, p_Wsum,
                                     -1.0f, p_part, B / 8);

    final_reduce_kernel<<<1, 256>>>(p_part, 2 * (B / 8), 1.0f / (float)B, (float*)d_out);
}